// round 1
// baseline (speedup 1.0000x reference)
#include <cuda_runtime.h>
#include <math.h>

// ---------------- scratch (static device allocations are allowed) ----------------
__device__ float g_h1[16777216];      // 32768*512 (reused: stage1 hidden, G1, P1(4096*2048))
__device__ float g_df[16777216];      // 32768*512
__device__ float g_ef[33652736];      // 32768*1027
__device__ float g_coords[65536];     // 32768*2
__device__ float g_imp[32768];
__device__ int   g_top[4096];         // 8*512
__device__ float g_pos[8192];         // 8*512*2
__device__ float g_states[4194304];   // 4096*1024
__device__ float g_proj[2097152];     // 4096*512

__device__ __forceinline__ float gelu_f(float x) {
    return 0.5f * x * (1.0f + erff(x * 0.70710678118654752440f));
}

// ---------------- generic tiled fp32 GEMM, 128x128x16, 8x8 per thread ----------------
// EPI: 0 = +bias, 1 = gelu(+bias), 2 = gelu(+bias + coords[m,0]*wtop[0,n] + coords[m,1]*wtop[1,n])
// NG:  true -> guard N (used for N=1027, scalar B loads / stores)
template<int EPI, bool NG>
__global__ void __launch_bounds__(256) gemm_k(
    const float* __restrict__ A, const float* __restrict__ B,
    const float* __restrict__ bias, float* __restrict__ C,
    int M, int N, int K, int ldb,
    const float* __restrict__ coords, const float* __restrict__ wtop)
{
    __shared__ float As[16][128];
    __shared__ float Bs[16][128];

    const int tid = threadIdx.x;
    const int bm  = blockIdx.y * 128;
    const int bn  = blockIdx.x * 128;
    const int tx  = tid & 15;          // 16 col-groups
    const int ty  = tid >> 4;          // 16 row-groups
    const int row = ty * 8;            // rows row..row+7
    // cols: {bn + tx*4 .. +3} and {bn + 64 + tx*4 .. +3}  (conflict-free smem reads)

    float acc[8][8];
    #pragma unroll
    for (int i = 0; i < 8; i++)
        #pragma unroll
        for (int j = 0; j < 8; j++) acc[i][j] = 0.0f;

    for (int k0 = 0; k0 < K; k0 += 16) {
        // load A tile 128x16 (coalesced float4, store transposed)
        #pragma unroll
        for (int i = 0; i < 2; i++) {
            int f  = tid + i * 256;         // 0..511
            int r  = f >> 2;                // 0..127
            int c4 = f & 3;                 // 0..3
            float4 v = *reinterpret_cast<const float4*>(A + (long)(bm + r) * K + k0 + c4 * 4);
            As[c4 * 4 + 0][r] = v.x;
            As[c4 * 4 + 1][r] = v.y;
            As[c4 * 4 + 2][r] = v.z;
            As[c4 * 4 + 3][r] = v.w;
        }
        // load B tile 16x128
        if (!NG) {
            #pragma unroll
            for (int i = 0; i < 2; i++) {
                int f  = tid + i * 256;
                int r  = f >> 5;            // 0..15
                int c4 = f & 31;            // 0..31
                *reinterpret_cast<float4*>(&Bs[r][c4 * 4]) =
                    *reinterpret_cast<const float4*>(B + (long)(k0 + r) * ldb + bn + c4 * 4);
            }
        } else {
            #pragma unroll
            for (int i = 0; i < 8; i++) {
                int f = tid + i * 256;      // 0..2047
                int r = f >> 7;             // 0..15
                int c = f & 127;
                int gn = bn + c;
                Bs[r][c] = (gn < N) ? B[(long)(k0 + r) * ldb + gn] : 0.0f;
            }
        }
        __syncthreads();

        #pragma unroll
        for (int k = 0; k < 16; k++) {
            float a[8], b[8];
            float4 a0 = *reinterpret_cast<const float4*>(&As[k][row]);
            float4 a1 = *reinterpret_cast<const float4*>(&As[k][row + 4]);
            a[0]=a0.x; a[1]=a0.y; a[2]=a0.z; a[3]=a0.w;
            a[4]=a1.x; a[5]=a1.y; a[6]=a1.z; a[7]=a1.w;
            float4 b0 = *reinterpret_cast<const float4*>(&Bs[k][tx * 4]);
            float4 b1 = *reinterpret_cast<const float4*>(&Bs[k][64 + tx * 4]);
            b[0]=b0.x; b[1]=b0.y; b[2]=b0.z; b[3]=b0.w;
            b[4]=b1.x; b[5]=b1.y; b[6]=b1.z; b[7]=b1.w;
            #pragma unroll
            for (int i = 0; i < 8; i++)
                #pragma unroll
                for (int j = 0; j < 8; j++)
                    acc[i][j] = fmaf(a[i], b[j], acc[i][j]);
        }
        __syncthreads();
    }

    // epilogue
    float bs[8], w0[8], w1[8];
    #pragma unroll
    for (int h = 0; h < 2; h++)
        #pragma unroll
        for (int jj = 0; jj < 4; jj++) {
            int j = h * 4 + jj;
            int n = bn + h * 64 + tx * 4 + jj;
            bool ok = !NG || (n < N);
            bs[j] = ok ? bias[n] : 0.0f;
            if (EPI == 2) { w0[j] = ok ? wtop[n] : 0.0f; w1[j] = ok ? wtop[512 + n] : 0.0f; }
        }

    #pragma unroll
    for (int i = 0; i < 8; i++) {
        int gm = bm + row + i;
        float c0 = 0.0f, c1 = 0.0f;
        if (EPI == 2) { c0 = coords[(long)gm * 2]; c1 = coords[(long)gm * 2 + 1]; }
        #pragma unroll
        for (int h = 0; h < 2; h++) {
            int nb = bn + h * 64 + tx * 4;
            if (!NG) {
                float4 v;
                float t[4];
                #pragma unroll
                for (int jj = 0; jj < 4; jj++) {
                    int j = h * 4 + jj;
                    float val = acc[i][j] + bs[j];
                    if (EPI == 2) val += c0 * w0[j] + c1 * w1[j];
                    if (EPI >= 1) val = gelu_f(val);
                    t[jj] = val;
                }
                v.x = t[0]; v.y = t[1]; v.z = t[2]; v.w = t[3];
                *reinterpret_cast<float4*>(C + (long)gm * N + nb) = v;
            } else {
                #pragma unroll
                for (int jj = 0; jj < 4; jj++) {
                    int j = h * 4 + jj;
                    int n = nb + jj;
                    if (n < N) {
                        float val = acc[i][j] + bs[j];
                        if (EPI >= 1) val = gelu_f(val);
                        C[(long)gm * N + n] = val;
                    }
                }
            }
        }
    }
}

// ---------------- coords: (32768,512) @ (512,2) + bc ----------------
__global__ void __launch_bounds__(256) coords_k(
    const float* __restrict__ df, const float* __restrict__ Wc,
    const float* __restrict__ bc, float* __restrict__ coords)
{
    int r    = blockIdx.x * 8 + (threadIdx.x >> 5);
    int lane = threadIdx.x & 31;
    if (r >= 32768) return;
    const float* rowp = df + (long)r * 512;
    float c0 = 0.0f, c1 = 0.0f;
    for (int k = lane; k < 512; k += 32) {
        float v = rowp[k];
        c0 = fmaf(v, Wc[k * 2], c0);
        c1 = fmaf(v, Wc[k * 2 + 1], c1);
    }
    #pragma unroll
    for (int o = 16; o; o >>= 1) {
        c0 += __shfl_xor_sync(0xffffffffu, c0, o);
        c1 += __shfl_xor_sync(0xffffffffu, c1, o);
    }
    if (lane == 0) {
        coords[(long)r * 2]     = c0 + bc[0];
        coords[(long)r * 2 + 1] = c1 + bc[1];
    }
}

// ---------------- importance: row L2 norm over 1027 ----------------
__global__ void __launch_bounds__(256) imp_k(
    const float* __restrict__ ef, float* __restrict__ imp)
{
    int r    = blockIdx.x * 8 + (threadIdx.x >> 5);
    int lane = threadIdx.x & 31;
    if (r >= 32768) return;
    const float* rowp = ef + (long)r * 1027;
    float s = 0.0f;
    for (int k = lane; k < 1027; k += 32) {
        float v = rowp[k];
        s = fmaf(v, v, s);
    }
    #pragma unroll
    for (int o = 16; o; o >>= 1) s += __shfl_xor_sync(0xffffffffu, s, o);
    if (lane == 0) imp[r] = sqrtf(s);
}

// ---------------- top-512 of 4096 per batch (set only; ties -> smaller index) ----------------
__global__ void __launch_bounds__(1024) topk_k(
    const float* __restrict__ imp, int* __restrict__ top)
{
    __shared__ unsigned long long key[4096];
    int b   = blockIdx.x;
    int tid = threadIdx.x;
    for (int s = tid; s < 4096; s += 1024) {
        unsigned int bits = __float_as_uint(imp[b * 4096 + s]); // values >= 0
        key[s] = ((unsigned long long)(~bits) << 32) | (unsigned int)s;
    }
    for (int k = 2; k <= 4096; k <<= 1) {
        for (int j = k >> 1; j > 0; j >>= 1) {
            __syncthreads();
            for (int idx = tid; idx < 4096; idx += 1024) {
                int l = idx ^ j;
                if (l > idx) {
                    bool asc = ((idx & k) == 0);
                    unsigned long long a = key[idx], c = key[l];
                    if ((a > c) == asc) { key[idx] = c; key[l] = a; }
                }
            }
        }
    }
    __syncthreads();
    if (tid < 512) top[b * 512 + tid] = (int)(key[tid] & 0xffffffffu);
}

// ---------------- gather selected rows ----------------
__global__ void __launch_bounds__(256) gather_k(
    const float* __restrict__ ef, const int* __restrict__ top,
    float* __restrict__ pos, float* __restrict__ states)
{
    int rowi = blockIdx.x;          // 0..4095
    int b    = rowi >> 9;
    int s    = top[rowi];
    const float* src = ef + (long)(b * 4096 + s) * 1027;
    if (threadIdx.x < 2) pos[rowi * 2 + threadIdx.x] = src[threadIdx.x];
    for (int d = threadIdx.x; d < 1024; d += 256)
        states[(long)rowi * 1024 + d] = src[2 + d];
}

// ---------------- fused gaussian attention + einsum ----------------
// block: 32 grid points x all 512 entities; out tile 32x512
__global__ void __launch_bounds__(256) attn_k(
    const float* __restrict__ pos, const float* __restrict__ proj,
    float* __restrict__ out)
{
    extern __shared__ float sm[];
    float* spx  = sm;                  // 512
    float* spy  = spx + 512;           // 512
    float* sa   = spy + 512;           // 32*512
    float* rinv = sa + 32 * 512;       // 32

    const int b   = blockIdx.y;
    const int g0  = blockIdx.x * 32;
    const int tid = threadIdx.x;

    for (int n = tid; n < 512; n += 256) {
        spx[n] = pos[(b * 512 + n) * 2];
        spy[n] = pos[(b * 512 + n) * 2 + 1];
    }
    __syncthreads();

    for (int e = tid; e < 32 * 512; e += 256) {
        int i  = e >> 9;
        int n  = e & 511;
        int gi = g0 + i;
        float a = 0.0f;
        if (gi < 10000) {
            int ix = gi / 100, iy = gi - ix * 100;
            float gx = (ix == 99) ? 1.0f : -1.0f + (float)ix * (2.0f / 99.0f);
            float gy = (iy == 99) ? 1.0f : -1.0f + (float)iy * (2.0f / 99.0f);
            float dx = gx - spx[n];
            float dy = gy - spy[n];
            float sq = fmaf(dx, dx, dy * dy);
            a = expf(-sq / 0.1f);
        }
        sa[i * 512 + n] = a;
    }
    __syncthreads();

    int warp = tid >> 5, lane = tid & 31;
    for (int i = warp; i < 32; i += 8) {
        float s = 0.0f;
        for (int n = lane; n < 512; n += 32) s += sa[i * 512 + n];
        #pragma unroll
        for (int o = 16; o; o >>= 1) s += __shfl_xor_sync(0xffffffffu, s, o);
        if (lane == 0) rinv[i] = 1.0f / (s + 1e-8f);
    }
    __syncthreads();

    // 32x512 = sa(32x512) @ proj_b(512x512); thread: 4 rows x 16 cols (4 chunks of 4)
    const int ig = tid >> 5;           // 0..7 -> rows ig*4..+3
    const int dg = tid & 31;           // col chunks: dg*4 + q*128
    const float* pb = proj + (long)b * 512 * 512;
    float acc[4][16];
    #pragma unroll
    for (int i = 0; i < 4; i++)
        #pragma unroll
        for (int j = 0; j < 16; j++) acc[i][j] = 0.0f;

    #pragma unroll 2
    for (int n = 0; n < 512; n++) {
        float a0 = sa[(ig * 4 + 0) * 512 + n];
        float a1 = sa[(ig * 4 + 1) * 512 + n];
        float a2 = sa[(ig * 4 + 2) * 512 + n];
        float a3 = sa[(ig * 4 + 3) * 512 + n];
        const float* prow = pb + (long)n * 512 + dg * 4;
        #pragma unroll
        for (int q = 0; q < 4; q++) {
            float4 v = *reinterpret_cast<const float4*>(prow + q * 128);
            acc[0][q*4+0] = fmaf(a0, v.x, acc[0][q*4+0]);
            acc[0][q*4+1] = fmaf(a0, v.y, acc[0][q*4+1]);
            acc[0][q*4+2] = fmaf(a0, v.z, acc[0][q*4+2]);
            acc[0][q*4+3] = fmaf(a0, v.w, acc[0][q*4+3]);
            acc[1][q*4+0] = fmaf(a1, v.x, acc[1][q*4+0]);
            acc[1][q*4+1] = fmaf(a1, v.y, acc[1][q*4+1]);
            acc[1][q*4+2] = fmaf(a1, v.z, acc[1][q*4+2]);
            acc[1][q*4+3] = fmaf(a1, v.w, acc[1][q*4+3]);
            acc[2][q*4+0] = fmaf(a2, v.x, acc[2][q*4+0]);
            acc[2][q*4+1] = fmaf(a2, v.y, acc[2][q*4+1]);
            acc[2][q*4+2] = fmaf(a2, v.z, acc[2][q*4+2]);
            acc[2][q*4+3] = fmaf(a2, v.w, acc[2][q*4+3]);
            acc[3][q*4+0] = fmaf(a3, v.x, acc[3][q*4+0]);
            acc[3][q*4+1] = fmaf(a3, v.y, acc[3][q*4+1]);
            acc[3][q*4+2] = fmaf(a3, v.z, acc[3][q*4+2]);
            acc[3][q*4+3] = fmaf(a3, v.w, acc[3][q*4+3]);
        }
    }

    #pragma unroll
    for (int ii = 0; ii < 4; ii++) {
        int gi = g0 + ig * 4 + ii;
        if (gi < 10000) {
            float r = rinv[ig * 4 + ii];
            float* o = out + ((long)b * 10000 + gi) * 512 + dg * 4;
            #pragma unroll
            for (int q = 0; q < 4; q++) {
                float4 v;
                v.x = acc[ii][q*4+0] * r;
                v.y = acc[ii][q*4+1] * r;
                v.z = acc[ii][q*4+2] * r;
                v.w = acc[ii][q*4+3] * r;
                *reinterpret_cast<float4*>(o + q * 128) = v;
            }
        }
    }
}

// ---------------- launch ----------------
extern "C" void kernel_launch(void* const* d_in, const int* in_sizes, int n_in,
                              void* d_out, int out_size)
{
    const float* x   = (const float*)d_in[0];
    const float* W1  = (const float*)d_in[1];
    const float* b1  = (const float*)d_in[2];
    const float* W2  = (const float*)d_in[3];
    const float* b2  = (const float*)d_in[4];
    const float* Wc  = (const float*)d_in[5];
    const float* bc  = (const float*)d_in[6];
    const float* We1 = (const float*)d_in[7];
    const float* be1 = (const float*)d_in[8];
    const float* We2 = (const float*)d_in[9];
    const float* be2 = (const float*)d_in[10];
    const float* Wo1 = (const float*)d_in[11];
    const float* bo1 = (const float*)d_in[12];
    const float* Wo2 = (const float*)d_in[13];
    const float* bo2 = (const float*)d_in[14];
    float* out = (float*)d_out;

    float *h1, *df, *ef, *coords, *imp, *pos, *states, *proj;
    int* top;
    cudaGetSymbolAddress((void**)&h1,     g_h1);
    cudaGetSymbolAddress((void**)&df,     g_df);
    cudaGetSymbolAddress((void**)&ef,     g_ef);
    cudaGetSymbolAddress((void**)&coords, g_coords);
    cudaGetSymbolAddress((void**)&imp,    g_imp);
    cudaGetSymbolAddress((void**)&top,    g_top);
    cudaGetSymbolAddress((void**)&pos,    g_pos);
    cudaGetSymbolAddress((void**)&states, g_states);
    cudaGetSymbolAddress((void**)&proj,   g_proj);

    // 1) h1 = gelu(x @ W1 + b1)                       (32768,512,512)
    gemm_k<1,false><<<dim3(4,256), 256>>>(x,  W1, b1, h1, 32768, 512, 512, 512, nullptr, nullptr);
    // 2) df = gelu(h1 @ W2 + b2)
    gemm_k<1,false><<<dim3(4,256), 256>>>(h1, W2, b2, df, 32768, 512, 512, 512, nullptr, nullptr);
    // 3) coords = df @ Wc + bc
    coords_k<<<4096, 256>>>(df, Wc, bc, coords);
    // 4) h1 = gelu(df @ We1[2:,:] + coords @ We1[:2,:] + be1)
    gemm_k<2,false><<<dim3(4,256), 256>>>(df, We1 + 1024, be1, h1, 32768, 512, 512, 512, coords, We1);
    // 5) ef = h1 @ We2 + be2                          (32768,1027,512)
    gemm_k<0,true><<<dim3(9,256), 256>>>(h1, We2, be2, ef, 32768, 1027, 512, 1027, nullptr, nullptr);
    // 6) importance
    imp_k<<<4096, 256>>>(ef, imp);
    // 7) top-512 per batch
    topk_k<<<8, 1024>>>(imp, top);
    // 8) gather positions + states
    gather_k<<<4096, 256>>>(ef, top, pos, states);
    // 9) h1 = gelu(states @ Wo1 + bo1)                (4096,2048,1024)
    gemm_k<1,false><<<dim3(16,32), 256>>>(states, Wo1, bo1, h1, 4096, 2048, 1024, 2048, nullptr, nullptr);
    // 10) proj = h1 @ Wo2 + bo2                       (4096,512,2048)
    gemm_k<0,false><<<dim3(4,32), 256>>>(h1, Wo2, bo2, proj, 4096, 512, 2048, 512, nullptr, nullptr);
    // 11) fused gaussian attention + einsum -> out    (8,10000,512)
    cudaFuncSetAttribute(attn_k, cudaFuncAttributeMaxDynamicSharedMemorySize, 70656);
    attn_k<<<dim3(313, 8), 256, 69760>>>(pos, proj, out);
}

// round 2
// speedup vs baseline: 1.3210x; 1.3210x over previous
#include <cuda_runtime.h>
#include <math.h>

// ---------------- scratch ----------------
__device__ float g_h1[16777216];      // 32768*512 (reused; also 4096*2048)
__device__ float g_df[16777216];      // 32768*512
__device__ float g_ef[33652736];      // 32768*1027
__device__ float g_coords[65536];     // 32768*2
__device__ float g_imp[32768];
__device__ int   g_top[4096];         // 8*512
__device__ float g_pos[8192];         // 8*512*2
__device__ float g_states[4194304];   // 4096*1024
__device__ float g_proj[2097152];     // 4096*512

__device__ __forceinline__ float gelu_f(float x) {
    return 0.5f * x * (1.0f + erff(x * 0.70710678118654752440f));
}

// ---- packed fp32x2 helpers (bit-exact fp32, 2x FMA throughput) ----
__device__ __forceinline__ unsigned long long pack2(float x) {
    unsigned long long r;
    asm("mov.b64 %0, {%1, %1};" : "=l"(r) : "f"(x));
    return r;
}
__device__ __forceinline__ void fma2(unsigned long long& d,
                                     unsigned long long a,
                                     unsigned long long b) {
    asm("fma.rn.f32x2 %0, %1, %2, %0;" : "+l"(d) : "l"(a), "l"(b));
}
__device__ __forceinline__ float2 unpack2(unsigned long long p) {
    float2 f;
    asm("mov.b64 {%0, %1}, %2;" : "=f"(f.x), "=f"(f.y) : "l"(p));
    return f;
}

// ---------------- tiled fp32 GEMM, 128x128x16, 8x8 per thread, FFMA2 core ----------------
// EPI: 0 = +bias, 1 = gelu(+bias), 2 = gelu(+bias + coords[m,:] @ wtop[:2,n])
// NG:  true -> guard N (N=1027)
template<int EPI, bool NG>
__global__ void __launch_bounds__(256) gemm_k(
    const float* __restrict__ A, const float* __restrict__ B,
    const float* __restrict__ bias, float* __restrict__ C,
    int M, int N, int K, int ldb,
    const float* __restrict__ coords, const float* __restrict__ wtop)
{
    __shared__ __align__(16) unsigned long long As2[16][130]; // duplicated {a,a} pairs
    __shared__ __align__(16) float Bs[16][128];

    const int tid = threadIdx.x;
    const int bm  = blockIdx.y * 128;
    const int bn  = blockIdx.x * 128;
    const int tx  = tid & 15;
    const int ty  = tid >> 4;
    const int row = ty * 8;

    unsigned long long acc2[8][4];
    #pragma unroll
    for (int i = 0; i < 8; i++)
        #pragma unroll
        for (int p = 0; p < 4; p++) acc2[i][p] = 0ULL;

    // A-tile reg addressing: thread covers rows rA0, rA0+64, cols c4*4..+3 of the 16-wide tile
    const int rA0 = tid >> 2;
    const int cA4 = tid & 3;
    // B-tile (!NG): rows rB0, rB0+8, col group cB
    const int rB0 = tid >> 5;
    const int cB  = (tid & 31) * 4;
    // B-tile (NG): rows (tid>>7)+2*i, col tid&127
    const int rNG = tid >> 7;
    const int cNG = tid & 127;

    float4 ra0, ra1;
    float4 rb0, rb1;
    float  rbs[8];

    // prefetch first tile
    {
        ra0 = *reinterpret_cast<const float4*>(A + (size_t)(bm + rA0) * K + cA4 * 4);
        ra1 = *reinterpret_cast<const float4*>(A + (size_t)(bm + rA0 + 64) * K + cA4 * 4);
        if (!NG) {
            rb0 = *reinterpret_cast<const float4*>(B + (size_t)rB0 * ldb + bn + cB);
            rb1 = *reinterpret_cast<const float4*>(B + (size_t)(rB0 + 8) * ldb + bn + cB);
        } else {
            #pragma unroll
            for (int i = 0; i < 8; i++) {
                int r = rNG + i * 2;
                int gn = bn + cNG;
                rbs[i] = (gn < N) ? B[(size_t)r * ldb + gn] : 0.0f;
            }
        }
    }

    for (int k0 = 0; k0 < K; k0 += 16) {
        __syncthreads();
        // store prefetched tile to smem (A duplicated into pairs)
        As2[cA4 * 4 + 0][rA0] = pack2(ra0.x);
        As2[cA4 * 4 + 1][rA0] = pack2(ra0.y);
        As2[cA4 * 4 + 2][rA0] = pack2(ra0.z);
        As2[cA4 * 4 + 3][rA0] = pack2(ra0.w);
        As2[cA4 * 4 + 0][rA0 + 64] = pack2(ra1.x);
        As2[cA4 * 4 + 1][rA0 + 64] = pack2(ra1.y);
        As2[cA4 * 4 + 2][rA0 + 64] = pack2(ra1.z);
        As2[cA4 * 4 + 3][rA0 + 64] = pack2(ra1.w);
        if (!NG) {
            *reinterpret_cast<float4*>(&Bs[rB0][cB])     = rb0;
            *reinterpret_cast<float4*>(&Bs[rB0 + 8][cB]) = rb1;
        } else {
            #pragma unroll
            for (int i = 0; i < 8; i++) Bs[rNG + i * 2][cNG] = rbs[i];
        }
        __syncthreads();

        // prefetch next tile
        if (k0 + 16 < K) {
            int kn = k0 + 16;
            ra0 = *reinterpret_cast<const float4*>(A + (size_t)(bm + rA0) * K + kn + cA4 * 4);
            ra1 = *reinterpret_cast<const float4*>(A + (size_t)(bm + rA0 + 64) * K + kn + cA4 * 4);
            if (!NG) {
                rb0 = *reinterpret_cast<const float4*>(B + (size_t)(kn + rB0) * ldb + bn + cB);
                rb1 = *reinterpret_cast<const float4*>(B + (size_t)(kn + rB0 + 8) * ldb + bn + cB);
            } else {
                #pragma unroll
                for (int i = 0; i < 8; i++) {
                    int r = kn + rNG + i * 2;
                    int gn = bn + cNG;
                    rbs[i] = (gn < N) ? B[(size_t)r * ldb + gn] : 0.0f;
                }
            }
        }

        // compute
        #pragma unroll
        for (int k = 0; k < 16; k++) {
            ulonglong2 A0 = *reinterpret_cast<const ulonglong2*>(&As2[k][row]);
            ulonglong2 A1 = *reinterpret_cast<const ulonglong2*>(&As2[k][row + 2]);
            ulonglong2 A2 = *reinterpret_cast<const ulonglong2*>(&As2[k][row + 4]);
            ulonglong2 A3 = *reinterpret_cast<const ulonglong2*>(&As2[k][row + 6]);
            ulonglong2 B0 = *reinterpret_cast<const ulonglong2*>(&Bs[k][tx * 4]);
            ulonglong2 B1 = *reinterpret_cast<const ulonglong2*>(&Bs[k][64 + tx * 4]);
            unsigned long long ap[8] = {A0.x, A0.y, A1.x, A1.y, A2.x, A2.y, A3.x, A3.y};
            unsigned long long bp[4] = {B0.x, B0.y, B1.x, B1.y};
            #pragma unroll
            for (int i = 0; i < 8; i++) {
                fma2(acc2[i][0], ap[i], bp[0]);
                fma2(acc2[i][1], ap[i], bp[1]);
                fma2(acc2[i][2], ap[i], bp[2]);
                fma2(acc2[i][3], ap[i], bp[3]);
            }
        }
    }

    // unpack accumulators
    float acc[8][8];
    #pragma unroll
    for (int i = 0; i < 8; i++)
        #pragma unroll
        for (int p = 0; p < 4; p++) {
            float2 t = unpack2(acc2[i][p]);
            acc[i][p * 2 + 0] = t.x;
            acc[i][p * 2 + 1] = t.y;
        }

    // epilogue
    float bs[8], w0[8], w1[8];
    #pragma unroll
    for (int h = 0; h < 2; h++)
        #pragma unroll
        for (int jj = 0; jj < 4; jj++) {
            int j = h * 4 + jj;
            int n = bn + h * 64 + tx * 4 + jj;
            bool ok = !NG || (n < N);
            bs[j] = ok ? bias[n] : 0.0f;
            if (EPI == 2) { w0[j] = ok ? wtop[n] : 0.0f; w1[j] = ok ? wtop[512 + n] : 0.0f; }
        }

    #pragma unroll
    for (int i = 0; i < 8; i++) {
        int gm = bm + row + i;
        float c0 = 0.0f, c1 = 0.0f;
        if (EPI == 2) { c0 = coords[(size_t)gm * 2]; c1 = coords[(size_t)gm * 2 + 1]; }
        #pragma unroll
        for (int h = 0; h < 2; h++) {
            int nb = bn + h * 64 + tx * 4;
            if (!NG) {
                float t[4];
                #pragma unroll
                for (int jj = 0; jj < 4; jj++) {
                    int j = h * 4 + jj;
                    float val = acc[i][j] + bs[j];
                    if (EPI == 2) val += c0 * w0[j] + c1 * w1[j];
                    if (EPI >= 1) val = gelu_f(val);
                    t[jj] = val;
                }
                float4 v; v.x = t[0]; v.y = t[1]; v.z = t[2]; v.w = t[3];
                *reinterpret_cast<float4*>(C + (size_t)gm * N + nb) = v;
            } else {
                #pragma unroll
                for (int jj = 0; jj < 4; jj++) {
                    int j = h * 4 + jj;
                    int n = nb + jj;
                    if (n < N) {
                        float val = acc[i][j] + bs[j];
                        if (EPI >= 1) val = gelu_f(val);
                        C[(size_t)gm * N + n] = val;
                    }
                }
            }
        }
    }
}

// ---------------- coords: (32768,512) @ (512,2) + bc ----------------
__global__ void __launch_bounds__(256) coords_k(
    const float* __restrict__ df, const float* __restrict__ Wc,
    const float* __restrict__ bc, float* __restrict__ coords)
{
    int r    = blockIdx.x * 8 + (threadIdx.x >> 5);
    int lane = threadIdx.x & 31;
    if (r >= 32768) return;
    const float* rowp = df + (size_t)r * 512;
    float c0 = 0.0f, c1 = 0.0f;
    for (int k = lane; k < 512; k += 32) {
        float v = rowp[k];
        c0 = fmaf(v, Wc[k * 2], c0);
        c1 = fmaf(v, Wc[k * 2 + 1], c1);
    }
    #pragma unroll
    for (int o = 16; o; o >>= 1) {
        c0 += __shfl_xor_sync(0xffffffffu, c0, o);
        c1 += __shfl_xor_sync(0xffffffffu, c1, o);
    }
    if (lane == 0) {
        coords[(size_t)r * 2]     = c0 + bc[0];
        coords[(size_t)r * 2 + 1] = c1 + bc[1];
    }
}

// ---------------- importance: row L2 norm over 1027 ----------------
__global__ void __launch_bounds__(256) imp_k(
    const float* __restrict__ ef, float* __restrict__ imp)
{
    int r    = blockIdx.x * 8 + (threadIdx.x >> 5);
    int lane = threadIdx.x & 31;
    if (r >= 32768) return;
    const float* rowp = ef + (size_t)r * 1027;
    float s = 0.0f;
    for (int k = lane; k < 1027; k += 32) {
        float v = rowp[k];
        s = fmaf(v, v, s);
    }
    #pragma unroll
    for (int o = 16; o; o >>= 1) s += __shfl_xor_sync(0xffffffffu, s, o);
    if (lane == 0) imp[r] = sqrtf(s);
}

// ---------------- top-512 of 4096 per batch ----------------
__global__ void __launch_bounds__(1024) topk_k(
    const float* __restrict__ imp, int* __restrict__ top)
{
    __shared__ unsigned long long key[4096];
    int b   = blockIdx.x;
    int tid = threadIdx.x;
    for (int s = tid; s < 4096; s += 1024) {
        unsigned int bits = __float_as_uint(imp[b * 4096 + s]);
        key[s] = ((unsigned long long)(~bits) << 32) | (unsigned int)s;
    }
    for (int k = 2; k <= 4096; k <<= 1) {
        for (int j = k >> 1; j > 0; j >>= 1) {
            __syncthreads();
            for (int idx = tid; idx < 4096; idx += 1024) {
                int l = idx ^ j;
                if (l > idx) {
                    bool asc = ((idx & k) == 0);
                    unsigned long long a = key[idx], c = key[l];
                    if ((a > c) == asc) { key[idx] = c; key[l] = a; }
                }
            }
        }
    }
    __syncthreads();
    if (tid < 512) top[b * 512 + tid] = (int)(key[tid] & 0xffffffffu);
}

// ---------------- gather selected rows ----------------
__global__ void __launch_bounds__(256) gather_k(
    const float* __restrict__ ef, const int* __restrict__ top,
    float* __restrict__ pos, float* __restrict__ states)
{
    int rowi = blockIdx.x;
    int b    = rowi >> 9;
    int s    = top[rowi];
    const float* src = ef + (size_t)(b * 4096 + s) * 1027;
    if (threadIdx.x < 2) pos[rowi * 2 + threadIdx.x] = src[threadIdx.x];
    for (int d = threadIdx.x; d < 1024; d += 256)
        states[(size_t)rowi * 1024 + d] = src[2 + d];
}

// ---------------- fused gaussian attention + einsum (FFMA2 core) ----------------
__global__ void __launch_bounds__(256) attn_k(
    const float* __restrict__ pos, const float* __restrict__ proj,
    float* __restrict__ out)
{
    extern __shared__ float sm[];
    float* spx  = sm;                  // 512
    float* spy  = spx + 512;           // 512
    float* sa   = spy + 512;           // 32*512
    float* rinv = sa + 32 * 512;       // 32

    const int b   = blockIdx.y;
    const int g0  = blockIdx.x * 32;
    const int tid = threadIdx.x;

    for (int n = tid; n < 512; n += 256) {
        spx[n] = pos[(b * 512 + n) * 2];
        spy[n] = pos[(b * 512 + n) * 2 + 1];
    }
    __syncthreads();

    for (int e = tid; e < 32 * 512; e += 256) {
        int i  = e >> 9;
        int n  = e & 511;
        int gi = g0 + i;
        float a = 0.0f;
        if (gi < 10000) {
            int ix = gi / 100, iy = gi - ix * 100;
            float gx = (ix == 99) ? 1.0f : -1.0f + (float)ix * (2.0f / 99.0f);
            float gy = (iy == 99) ? 1.0f : -1.0f + (float)iy * (2.0f / 99.0f);
            float dx = gx - spx[n];
            float dy = gy - spy[n];
            float sq = fmaf(dx, dx, dy * dy);
            a = expf(-sq / 0.1f);
        }
        sa[i * 512 + n] = a;
    }
    __syncthreads();

    int warp = tid >> 5, lane = tid & 31;
    for (int i = warp; i < 32; i += 8) {
        float s = 0.0f;
        for (int n = lane; n < 512; n += 32) s += sa[i * 512 + n];
        #pragma unroll
        for (int o = 16; o; o >>= 1) s += __shfl_xor_sync(0xffffffffu, s, o);
        if (lane == 0) rinv[i] = 1.0f / (s + 1e-8f);
    }
    __syncthreads();

    // 32x512 = sa(32x512) @ proj_b(512x512); thread: 4 rows x 16 cols (8 pairs)
    const int ig = tid >> 5;           // rows ig*4..+3
    const int dg = tid & 31;           // cols dg*4 + q*128
    const float* pb = proj + (size_t)b * 512 * 512;
    unsigned long long acc[4][8];
    #pragma unroll
    for (int i = 0; i < 4; i++)
        #pragma unroll
        for (int j = 0; j < 8; j++) acc[i][j] = 0ULL;

    #pragma unroll 2
    for (int n = 0; n < 512; n++) {
        unsigned long long pa0 = pack2(sa[(ig * 4 + 0) * 512 + n]);
        unsigned long long pa1 = pack2(sa[(ig * 4 + 1) * 512 + n]);
        unsigned long long pa2 = pack2(sa[(ig * 4 + 2) * 512 + n]);
        unsigned long long pa3 = pack2(sa[(ig * 4 + 3) * 512 + n]);
        const float* prow = pb + (size_t)n * 512 + dg * 4;
        #pragma unroll
        for (int q = 0; q < 4; q++) {
            ulonglong2 v = *reinterpret_cast<const ulonglong2*>(prow + q * 128);
            fma2(acc[0][q * 2],     pa0, v.x);
            fma2(acc[0][q * 2 + 1], pa0, v.y);
            fma2(acc[1][q * 2],     pa1, v.x);
            fma2(acc[1][q * 2 + 1], pa1, v.y);
            fma2(acc[2][q * 2],     pa2, v.x);
            fma2(acc[2][q * 2 + 1], pa2, v.y);
            fma2(acc[3][q * 2],     pa3, v.x);
            fma2(acc[3][q * 2 + 1], pa3, v.y);
        }
    }

    #pragma unroll
    for (int ii = 0; ii < 4; ii++) {
        int gi = g0 + ig * 4 + ii;
        if (gi < 10000) {
            float r = rinv[ig * 4 + ii];
            float* o = out + ((size_t)b * 10000 + gi) * 512 + dg * 4;
            #pragma unroll
            for (int q = 0; q < 4; q++) {
                float2 t0 = unpack2(acc[ii][q * 2]);
                float2 t1 = unpack2(acc[ii][q * 2 + 1]);
                float4 v;
                v.x = t0.x * r;
                v.y = t0.y * r;
                v.z = t1.x * r;
                v.w = t1.y * r;
                *reinterpret_cast<float4*>(o + q * 128) = v;
            }
        }
    }
}

// ---------------- launch ----------------
extern "C" void kernel_launch(void* const* d_in, const int* in_sizes, int n_in,
                              void* d_out, int out_size)
{
    const float* x   = (const float*)d_in[0];
    const float* W1  = (const float*)d_in[1];
    const float* b1  = (const float*)d_in[2];
    const float* W2  = (const float*)d_in[3];
    const float* b2  = (const float*)d_in[4];
    const float* Wc  = (const float*)d_in[5];
    const float* bc  = (const float*)d_in[6];
    const float* We1 = (const float*)d_in[7];
    const float* be1 = (const float*)d_in[8];
    const float* We2 = (const float*)d_in[9];
    const float* be2 = (const float*)d_in[10];
    const float* Wo1 = (const float*)d_in[11];
    const float* bo1 = (const float*)d_in[12];
    const float* Wo2 = (const float*)d_in[13];
    const float* bo2 = (const float*)d_in[14];
    float* out = (float*)d_out;

    float *h1, *df, *ef, *coords, *imp, *pos, *states, *proj;
    int* top;
    cudaGetSymbolAddress((void**)&h1,     g_h1);
    cudaGetSymbolAddress((void**)&df,     g_df);
    cudaGetSymbolAddress((void**)&ef,     g_ef);
    cudaGetSymbolAddress((void**)&coords, g_coords);
    cudaGetSymbolAddress((void**)&imp,    g_imp);
    cudaGetSymbolAddress((void**)&top,    g_top);
    cudaGetSymbolAddress((void**)&pos,    g_pos);
    cudaGetSymbolAddress((void**)&states, g_states);
    cudaGetSymbolAddress((void**)&proj,   g_proj);

    // 1) h1 = gelu(x @ W1 + b1)
    gemm_k<1,false><<<dim3(4,256), 256>>>(x,  W1, b1, h1, 32768, 512, 512, 512, nullptr, nullptr);
    // 2) df = gelu(h1 @ W2 + b2)
    gemm_k<1,false><<<dim3(4,256), 256>>>(h1, W2, b2, df, 32768, 512, 512, 512, nullptr, nullptr);
    // 3) coords = df @ Wc + bc
    coords_k<<<4096, 256>>>(df, Wc, bc, coords);
    // 4) h1 = gelu(df @ We1[2:,:] + coords @ We1[:2,:] + be1)
    gemm_k<2,false><<<dim3(4,256), 256>>>(df, We1 + 1024, be1, h1, 32768, 512, 512, 512, coords, We1);
    // 5) ef = h1 @ We2 + be2
    gemm_k<0,true><<<dim3(9,256), 256>>>(h1, We2, be2, ef, 32768, 1027, 512, 1027, nullptr, nullptr);
    // 6) importance
    imp_k<<<4096, 256>>>(ef, imp);
    // 7) top-512 per batch
    topk_k<<<8, 1024>>>(imp, top);
    // 8) gather
    gather_k<<<4096, 256>>>(ef, top, pos, states);
    // 9) h1 = gelu(states @ Wo1 + bo1)   (4096,2048,1024)
    gemm_k<1,false><<<dim3(16,32), 256>>>(states, Wo1, bo1, h1, 4096, 2048, 1024, 2048, nullptr, nullptr);
    // 10) proj = h1 @ Wo2 + bo2          (4096,512,2048)
    gemm_k<0,false><<<dim3(4,32), 256>>>(h1, Wo2, bo2, proj, 4096, 512, 2048, 512, nullptr, nullptr);
    // 11) fused gaussian attention + einsum
    cudaFuncSetAttribute(attn_k, cudaFuncAttributeMaxDynamicSharedMemorySize, 70656);
    attn_k<<<dim3(313, 8), 256, 69760>>>(pos, proj, out);
}

// round 5
// speedup vs baseline: 1.6524x; 1.2508x over previous
#include <cuda_runtime.h>
#include <math.h>

// ---------------- scratch ----------------
__device__ float g_h1[16777216];      // 32768*512 (reused; also 4096*2048)
__device__ float g_df[16777216];      // 32768*512
__device__ float g_ef[33652736];      // 32768*1027
__device__ float g_coords[65536];     // 32768*2
__device__ float g_imp[32768];
__device__ int   g_top[4096];         // 8*512
__device__ float g_pos[8192];         // 8*512*2
__device__ float g_states[4194304];   // 4096*1024
__device__ float g_proj[2097152];     // 4096*512
__device__ float g_We2p[589824];      // 512*1152 padded We2

__device__ __forceinline__ float gelu_f(float x) {
    return 0.5f * x * (1.0f + erff(x * 0.70710678118654752440f));
}

// ---- packed fp32x2 helpers (bit-exact fp32, 2x FMA throughput) ----
__device__ __forceinline__ unsigned long long pack2(float x) {
    unsigned long long r;
    asm("mov.b64 %0, {%1, %1};" : "=l"(r) : "f"(x));
    return r;
}
__device__ __forceinline__ void fma2(unsigned long long& d,
                                     unsigned long long a,
                                     unsigned long long b) {
    asm("fma.rn.f32x2 %0, %1, %2, %0;" : "+l"(d) : "l"(a), "l"(b));
}
__device__ __forceinline__ float2 unpack2(unsigned long long p) {
    float2 f;
    asm("mov.b64 {%0, %1}, %2;" : "=f"(f.x), "=f"(f.y) : "l"(p));
    return f;
}

// ---------------- pad We2 (512,1027) -> (512,1152) zero-filled ----------------
__global__ void __launch_bounds__(256) padB_k(const float* __restrict__ src,
                                              float* __restrict__ dst)
{
    int i = blockIdx.x * 256 + threadIdx.x;     // over 512*1152
    if (i >= 512 * 1152) return;
    int r = i / 1152, c = i - r * 1152;
    dst[i] = (c < 1027) ? src[r * 1027 + c] : 0.0f;
}

// ---------------- tiled fp32 GEMM, 128x128x16, 8x8 per thread, FFMA2 core ----------------
// EPI: 0 = +bias, 1 = gelu(+bias), 2 = gelu(+bias + coords[m,:] @ wtop[:2,n])
// NG:  true -> guard N on bias load + stores only (B must be padded to ldb)
template<int EPI, bool NG>
__global__ void __launch_bounds__(256, 2) gemm_k(
    const float* __restrict__ A, const float* __restrict__ B,
    const float* __restrict__ bias, float* __restrict__ C,
    int M, int N, int K, int ldb,
    const float* __restrict__ coords, const float* __restrict__ wtop)
{
    __shared__ __align__(16) unsigned long long As2[16][130]; // duplicated {a,a} pairs
    __shared__ __align__(16) float Bs[16][128];

    const int tid = threadIdx.x;
    const int bm  = blockIdx.y * 128;
    const int bn  = blockIdx.x * 128;
    const int tx  = tid & 15;
    const int ty  = tid >> 4;
    const int row = ty * 8;

    unsigned long long acc2[8][4];
    #pragma unroll
    for (int i = 0; i < 8; i++)
        #pragma unroll
        for (int p = 0; p < 4; p++) acc2[i][p] = 0ULL;

    const int rA0 = tid >> 2;
    const int cA4 = tid & 3;
    const int rB0 = tid >> 5;
    const int cB  = (tid & 31) * 4;

    float4 ra0, ra1, rb0, rb1;

    // prefetch first tile
    ra0 = *reinterpret_cast<const float4*>(A + (size_t)(bm + rA0) * K + cA4 * 4);
    ra1 = *reinterpret_cast<const float4*>(A + (size_t)(bm + rA0 + 64) * K + cA4 * 4);
    rb0 = *reinterpret_cast<const float4*>(B + (size_t)rB0 * ldb + bn + cB);
    rb1 = *reinterpret_cast<const float4*>(B + (size_t)(rB0 + 8) * ldb + bn + cB);

    for (int k0 = 0; k0 < K; k0 += 16) {
        __syncthreads();
        As2[cA4 * 4 + 0][rA0] = pack2(ra0.x);
        As2[cA4 * 4 + 1][rA0] = pack2(ra0.y);
        As2[cA4 * 4 + 2][rA0] = pack2(ra0.z);
        As2[cA4 * 4 + 3][rA0] = pack2(ra0.w);
        As2[cA4 * 4 + 0][rA0 + 64] = pack2(ra1.x);
        As2[cA4 * 4 + 1][rA0 + 64] = pack2(ra1.y);
        As2[cA4 * 4 + 2][rA0 + 64] = pack2(ra1.z);
        As2[cA4 * 4 + 3][rA0 + 64] = pack2(ra1.w);
        *reinterpret_cast<float4*>(&Bs[rB0][cB])     = rb0;
        *reinterpret_cast<float4*>(&Bs[rB0 + 8][cB]) = rb1;
        __syncthreads();

        if (k0 + 16 < K) {
            int kn = k0 + 16;
            ra0 = *reinterpret_cast<const float4*>(A + (size_t)(bm + rA0) * K + kn + cA4 * 4);
            ra1 = *reinterpret_cast<const float4*>(A + (size_t)(bm + rA0 + 64) * K + kn + cA4 * 4);
            rb0 = *reinterpret_cast<const float4*>(B + (size_t)(kn + rB0) * ldb + bn + cB);
            rb1 = *reinterpret_cast<const float4*>(B + (size_t)(kn + rB0 + 8) * ldb + bn + cB);
        }

        #pragma unroll
        for (int k = 0; k < 16; k++) {
            ulonglong2 A0 = *reinterpret_cast<const ulonglong2*>(&As2[k][row]);
            ulonglong2 A1 = *reinterpret_cast<const ulonglong2*>(&As2[k][row + 2]);
            ulonglong2 A2 = *reinterpret_cast<const ulonglong2*>(&As2[k][row + 4]);
            ulonglong2 A3 = *reinterpret_cast<const ulonglong2*>(&As2[k][row + 6]);
            ulonglong2 B0 = *reinterpret_cast<const ulonglong2*>(&Bs[k][tx * 4]);
            ulonglong2 B1 = *reinterpret_cast<const ulonglong2*>(&Bs[k][64 + tx * 4]);
            fma2(acc2[0][0], A0.x, B0.x); fma2(acc2[0][1], A0.x, B0.y);
            fma2(acc2[0][2], A0.x, B1.x); fma2(acc2[0][3], A0.x, B1.y);
            fma2(acc2[1][0], A0.y, B0.x); fma2(acc2[1][1], A0.y, B0.y);
            fma2(acc2[1][2], A0.y, B1.x); fma2(acc2[1][3], A0.y, B1.y);
            fma2(acc2[2][0], A1.x, B0.x); fma2(acc2[2][1], A1.x, B0.y);
            fma2(acc2[2][2], A1.x, B1.x); fma2(acc2[2][3], A1.x, B1.y);
            fma2(acc2[3][0], A1.y, B0.x); fma2(acc2[3][1], A1.y, B0.y);
            fma2(acc2[3][2], A1.y, B1.x); fma2(acc2[3][3], A1.y, B1.y);
            fma2(acc2[4][0], A2.x, B0.x); fma2(acc2[4][1], A2.x, B0.y);
            fma2(acc2[4][2], A2.x, B1.x); fma2(acc2[4][3], A2.x, B1.y);
            fma2(acc2[5][0], A2.y, B0.x); fma2(acc2[5][1], A2.y, B0.y);
            fma2(acc2[5][2], A2.y, B1.x); fma2(acc2[5][3], A2.y, B1.y);
            fma2(acc2[6][0], A3.x, B0.x); fma2(acc2[6][1], A3.x, B0.y);
            fma2(acc2[6][2], A3.x, B1.x); fma2(acc2[6][3], A3.x, B1.y);
            fma2(acc2[7][0], A3.y, B0.x); fma2(acc2[7][1], A3.y, B0.y);
            fma2(acc2[7][2], A3.y, B1.x); fma2(acc2[7][3], A3.y, B1.y);
        }
    }

    // unpack accumulators
    float acc[8][8];
    #pragma unroll
    for (int i = 0; i < 8; i++)
        #pragma unroll
        for (int p = 0; p < 4; p++) {
            float2 t = unpack2(acc2[i][p]);
            acc[i][p * 2 + 0] = t.x;
            acc[i][p * 2 + 1] = t.y;
        }

    // epilogue
    float bs[8], w0[8], w1[8];
    #pragma unroll
    for (int h = 0; h < 2; h++)
        #pragma unroll
        for (int jj = 0; jj < 4; jj++) {
            int j = h * 4 + jj;
            int n = bn + h * 64 + tx * 4 + jj;
            bool ok = !NG || (n < N);
            bs[j] = ok ? bias[n] : 0.0f;
            if (EPI == 2) { w0[j] = ok ? wtop[n] : 0.0f; w1[j] = ok ? wtop[512 + n] : 0.0f; }
        }

    #pragma unroll
    for (int i = 0; i < 8; i++) {
        int gm = bm + row + i;
        float c0 = 0.0f, c1 = 0.0f;
        if (EPI == 2) { c0 = coords[(size_t)gm * 2]; c1 = coords[(size_t)gm * 2 + 1]; }
        #pragma unroll
        for (int h = 0; h < 2; h++) {
            int nb = bn + h * 64 + tx * 4;
            if (!NG) {
                float t[4];
                #pragma unroll
                for (int jj = 0; jj < 4; jj++) {
                    int j = h * 4 + jj;
                    float val = acc[i][j] + bs[j];
                    if (EPI == 2) val += c0 * w0[j] + c1 * w1[j];
                    if (EPI >= 1) val = gelu_f(val);
                    t[jj] = val;
                }
                float4 v; v.x = t[0]; v.y = t[1]; v.z = t[2]; v.w = t[3];
                *reinterpret_cast<float4*>(C + (size_t)gm * N + nb) = v;
            } else {
                #pragma unroll
                for (int jj = 0; jj < 4; jj++) {
                    int j = h * 4 + jj;
                    int n = nb + jj;
                    if (n < N) {
                        float val = acc[i][j] + bs[j];
                        if (EPI >= 1) val = gelu_f(val);
                        C[(size_t)gm * N + n] = val;
                    }
                }
            }
        }
    }
}

// ---------------- coords: (32768,512) @ (512,2) + bc ----------------
__global__ void __launch_bounds__(256) coords_k(
    const float* __restrict__ df, const float* __restrict__ Wc,
    const float* __restrict__ bc, float* __restrict__ coords)
{
    int r    = blockIdx.x * 8 + (threadIdx.x >> 5);
    int lane = threadIdx.x & 31;
    if (r >= 32768) return;
    const float* rowp = df + (size_t)r * 512;
    float c0 = 0.0f, c1 = 0.0f;
    for (int k = lane; k < 512; k += 32) {
        float v = rowp[k];
        c0 = fmaf(v, Wc[k * 2], c0);
        c1 = fmaf(v, Wc[k * 2 + 1], c1);
    }
    #pragma unroll
    for (int o = 16; o; o >>= 1) {
        c0 += __shfl_xor_sync(0xffffffffu, c0, o);
        c1 += __shfl_xor_sync(0xffffffffu, c1, o);
    }
    if (lane == 0) {
        coords[(size_t)r * 2]     = c0 + bc[0];
        coords[(size_t)r * 2 + 1] = c1 + bc[1];
    }
}

// ---------------- importance: row L2 norm over 1027 ----------------
__global__ void __launch_bounds__(256) imp_k(
    const float* __restrict__ ef, float* __restrict__ imp)
{
    int r    = blockIdx.x * 8 + (threadIdx.x >> 5);
    int lane = threadIdx.x & 31;
    if (r >= 32768) return;
    const float* rowp = ef + (size_t)r * 1027;
    float s = 0.0f;
    for (int k = lane; k < 1027; k += 32) {
        float v = rowp[k];
        s = fmaf(v, v, s);
    }
    #pragma unroll
    for (int o = 16; o; o >>= 1) s += __shfl_xor_sync(0xffffffffu, s, o);
    if (lane == 0) imp[r] = sqrtf(s);
}

// ---------------- top-512 of 4096 per batch ----------------
__global__ void __launch_bounds__(1024) topk_k(
    const float* __restrict__ imp, int* __restrict__ top)
{
    __shared__ unsigned long long key[4096];
    int b   = blockIdx.x;
    int tid = threadIdx.x;
    for (int s = tid; s < 4096; s += 1024) {
        unsigned int bits = __float_as_uint(imp[b * 4096 + s]);
        key[s] = ((unsigned long long)(~bits) << 32) | (unsigned int)s;
    }
    for (int k = 2; k <= 4096; k <<= 1) {
        for (int j = k >> 1; j > 0; j >>= 1) {
            __syncthreads();
            for (int idx = tid; idx < 4096; idx += 1024) {
                int l = idx ^ j;
                if (l > idx) {
                    bool asc = ((idx & k) == 0);
                    unsigned long long a = key[idx], c = key[l];
                    if ((a > c) == asc) { key[idx] = c; key[l] = a; }
                }
            }
        }
    }
    __syncthreads();
    if (tid < 512) top[b * 512 + tid] = (int)(key[tid] & 0xffffffffu);
}

// ---------------- gather selected rows ----------------
__global__ void __launch_bounds__(256) gather_k(
    const float* __restrict__ ef, const int* __restrict__ top,
    float* __restrict__ pos, float* __restrict__ states)
{
    int rowi = blockIdx.x;
    int b    = rowi >> 9;
    int s    = top[rowi];
    const float* src = ef + (size_t)(b * 4096 + s) * 1027;
    if (threadIdx.x < 2) pos[rowi * 2 + threadIdx.x] = src[threadIdx.x];
    for (int d = threadIdx.x; d < 1024; d += 256)
        states[(size_t)rowi * 1024 + d] = src[2 + d];
}

// ---------------- fused gaussian attention + einsum (FFMA2 core) ----------------
__global__ void __launch_bounds__(256, 2) attn_k(
    const float* __restrict__ pos, const float* __restrict__ proj,
    float* __restrict__ out)
{
    extern __shared__ float sm[];
    float* spx  = sm;                  // 512
    float* spy  = spx + 512;           // 512
    float* sa   = spy + 512;           // 32*512
    float* rinv = sa + 32 * 512;       // 32

    const int b   = blockIdx.y;
    const int g0  = blockIdx.x * 32;
    const int tid = threadIdx.x;

    for (int n = tid; n < 512; n += 256) {
        spx[n] = pos[(b * 512 + n) * 2];
        spy[n] = pos[(b * 512 + n) * 2 + 1];
    }
    __syncthreads();

    for (int e = tid; e < 32 * 512; e += 256) {
        int i  = e >> 9;
        int n  = e & 511;
        int gi = g0 + i;
        float a = 0.0f;
        if (gi < 10000) {
            int ix = gi / 100, iy = gi - ix * 100;
            float gx = (ix == 99) ? 1.0f : -1.0f + (float)ix * (2.0f / 99.0f);
            float gy = (iy == 99) ? 1.0f : -1.0f + (float)iy * (2.0f / 99.0f);
            float dx = gx - spx[n];
            float dy = gy - spy[n];
            float sq = fmaf(dx, dx, dy * dy);
            a = expf(-sq / 0.1f);
        }
        sa[i * 512 + n] = a;
    }
    __syncthreads();

    int warp = tid >> 5, lane = tid & 31;
    for (int i = warp; i < 32; i += 8) {
        float s = 0.0f;
        for (int n = lane; n < 512; n += 32) s += sa[i * 512 + n];
        #pragma unroll
        for (int o = 16; o; o >>= 1) s += __shfl_xor_sync(0xffffffffu, s, o);
        if (lane == 0) rinv[i] = 1.0f / (s + 1e-8f);
    }
    __syncthreads();

    const int ig = tid >> 5;           // rows ig*4..+3
    const int dg = tid & 31;           // cols dg*4 + q*128
    const float* pb = proj + (size_t)b * 512 * 512;
    unsigned long long acc[4][8];
    #pragma unroll
    for (int i = 0; i < 4; i++)
        #pragma unroll
        for (int j = 0; j < 8; j++) acc[i][j] = 0ULL;

    #pragma unroll 2
    for (int n = 0; n < 512; n++) {
        unsigned long long pa0 = pack2(sa[(ig * 4 + 0) * 512 + n]);
        unsigned long long pa1 = pack2(sa[(ig * 4 + 1) * 512 + n]);
        unsigned long long pa2 = pack2(sa[(ig * 4 + 2) * 512 + n]);
        unsigned long long pa3 = pack2(sa[(ig * 4 + 3) * 512 + n]);
        const float* prow = pb + (size_t)n * 512 + dg * 4;
        #pragma unroll
        for (int q = 0; q < 4; q++) {
            ulonglong2 v = *reinterpret_cast<const ulonglong2*>(prow + q * 128);
            fma2(acc[0][q * 2],     pa0, v.x);
            fma2(acc[0][q * 2 + 1], pa0, v.y);
            fma2(acc[1][q * 2],     pa1, v.x);
            fma2(acc[1][q * 2 + 1], pa1, v.y);
            fma2(acc[2][q * 2],     pa2, v.x);
            fma2(acc[2][q * 2 + 1], pa2, v.y);
            fma2(acc[3][q * 2],     pa3, v.x);
            fma2(acc[3][q * 2 + 1], pa3, v.y);
        }
    }

    #pragma unroll
    for (int ii = 0; ii < 4; ii++) {
        int gi = g0 + ig * 4 + ii;
        if (gi < 10000) {
            float r = rinv[ig * 4 + ii];
            float* o = out + ((size_t)b * 10000 + gi) * 512 + dg * 4;
            #pragma unroll
            for (int q = 0; q < 4; q++) {
                float2 t0 = unpack2(acc[ii][q * 2]);
                float2 t1 = unpack2(acc[ii][q * 2 + 1]);
                float4 v;
                v.x = t0.x * r;
                v.y = t0.y * r;
                v.z = t1.x * r;
                v.w = t1.y * r;
                *reinterpret_cast<float4*>(o + q * 128) = v;
            }
        }
    }
}

// ---------------- launch ----------------
extern "C" void kernel_launch(void* const* d_in, const int* in_sizes, int n_in,
                              void* d_out, int out_size)
{
    const float* x   = (const float*)d_in[0];
    const float* W1  = (const float*)d_in[1];
    const float* b1  = (const float*)d_in[2];
    const float* W2  = (const float*)d_in[3];
    const float* b2  = (const float*)d_in[4];
    const float* Wc  = (const float*)d_in[5];
    const float* bc  = (const float*)d_in[6];
    const float* We1 = (const float*)d_in[7];
    const float* be1 = (const float*)d_in[8];
    const float* We2 = (const float*)d_in[9];
    const float* be2 = (const float*)d_in[10];
    const float* Wo1 = (const float*)d_in[11];
    const float* bo1 = (const float*)d_in[12];
    const float* Wo2 = (const float*)d_in[13];
    const float* bo2 = (const float*)d_in[14];
    float* out = (float*)d_out;

    float *h1, *df, *ef, *coords, *imp, *pos, *states, *proj, *We2p;
    int* top;
    cudaGetSymbolAddress((void**)&h1,     g_h1);
    cudaGetSymbolAddress((void**)&df,     g_df);
    cudaGetSymbolAddress((void**)&ef,     g_ef);
    cudaGetSymbolAddress((void**)&coords, g_coords);
    cudaGetSymbolAddress((void**)&imp,    g_imp);
    cudaGetSymbolAddress((void**)&top,    g_top);
    cudaGetSymbolAddress((void**)&pos,    g_pos);
    cudaGetSymbolAddress((void**)&states, g_states);
    cudaGetSymbolAddress((void**)&proj,   g_proj);
    cudaGetSymbolAddress((void**)&We2p,   g_We2p);

    // 0) pad We2 -> (512,1152)
    padB_k<<<2304, 256>>>(We2, We2p);
    // 1) h1 = gelu(x @ W1 + b1)
    gemm_k<1,false><<<dim3(4,256), 256>>>(x,  W1, b1, h1, 32768, 512, 512, 512, nullptr, nullptr);
    // 2) df = gelu(h1 @ W2 + b2)
    gemm_k<1,false><<<dim3(4,256), 256>>>(h1, W2, b2, df, 32768, 512, 512, 512, nullptr, nullptr);
    // 3) coords = df @ Wc + bc
    coords_k<<<4096, 256>>>(df, Wc, bc, coords);
    // 4) h1 = gelu(df @ We1[2:,:] + coords @ We1[:2,:] + be1)
    gemm_k<2,false><<<dim3(4,256), 256>>>(df, We1 + 1024, be1, h1, 32768, 512, 512, 512, coords, We1);
    // 5) ef = h1 @ We2 + be2   (padded B)
    gemm_k<0,true><<<dim3(9,256), 256>>>(h1, We2p, be2, ef, 32768, 1027, 512, 1152, nullptr, nullptr);
    // 6) importance
    imp_k<<<4096, 256>>>(ef, imp);
    // 7) top-512 per batch
    topk_k<<<8, 1024>>>(imp, top);
    // 8) gather
    gather_k<<<4096, 256>>>(ef, top, pos, states);
    // 9) h1 = gelu(states @ Wo1 + bo1)   (4096,2048,1024)
    gemm_k<1,false><<<dim3(16,32), 256>>>(states, Wo1, bo1, h1, 4096, 2048, 1024, 2048, nullptr, nullptr);
    // 10) proj = h1 @ Wo2 + bo2          (4096,512,2048)
    gemm_k<0,false><<<dim3(4,32), 256>>>(h1, Wo2, bo2, proj, 4096, 512, 2048, 512, nullptr, nullptr);
    // 11) fused gaussian attention + einsum
    cudaFuncSetAttribute(attn_k, cudaFuncAttributeMaxDynamicSharedMemorySize, 70656);
    attn_k<<<dim3(313, 8), 256, 69760>>>(pos, proj, out);
}